// round 5
// baseline (speedup 1.0000x reference)
#include <cuda_runtime.h>
#include <math.h>

#define BATCH  2
#define SEQ    384
#define EMB    512
#define NHEADS 8
#define HD     64
#define NBH    16      // BATCH*NHEADS
#define MR     768     // BATCH*SEQ

// Scratch (allocation-free rule: __device__ globals)
__device__ float g_q[NBH * SEQ * HD];   // normalized q-hat, [bh][l][64]
__device__ float g_k[NBH * SEQ * HD];   // normalized k-hat
__device__ float g_v[NBH * SEQ * HD];   // raw v
__device__ float g_ctx[NBH * SEQ * HD]; // attention output

// ---------------------------------------------------------------------------
// Packed fp32x2 helpers (Blackwell f32x2 pipe: 2 MACs per FFMA2 instruction)
// ---------------------------------------------------------------------------
typedef unsigned long long u64;

__device__ __forceinline__ u64 f2pk(float lo, float hi) {
    u64 r; asm("mov.b64 %0,{%1,%2};" : "=l"(r) : "f"(lo), "f"(hi)); return r;
}
__device__ __forceinline__ void f2upk(u64 v, float& lo, float& hi) {
    asm("mov.b64 {%0,%1},%2;" : "=f"(lo), "=f"(hi) : "l"(v));
}
__device__ __forceinline__ u64 f2fma(u64 a, u64 b, u64 c) {
    u64 d; asm("fma.rn.f32x2 %0,%1,%2,%3;" : "=l"(d) : "l"(a), "l"(b), "l"(c)); return d;
}
__device__ __forceinline__ u64 f2mul(u64 a, u64 b) {
    u64 d; asm("mul.rn.f32x2 %0,%1,%2;" : "=l"(d) : "l"(a), "l"(b)); return d;
}
__device__ __forceinline__ u64 f2add(u64 a, u64 b) {
    u64 d; asm("add.rn.f32x2 %0,%1,%2;" : "=l"(d) : "l"(a), "l"(b)); return d;
}

// ---------------------------------------------------------------------------
// GEMM: C = A @ W^T.  M=768, N=512, K=512.
// BM=64, BN=64, BK=16, 128 threads, 8x4 microtile, row-pairs packed f32x2,
// B stored duplicated in smem so packed b operands load directly (no dup MOVs).
// Double-buffered smem, 1 syncthreads per k-tile.
// PERM_OUT: scatter to [bh][l][64] layout (+ fused quaternion normalization).
// PERM_A:   gather A from g_ctx in [bh][l][64] layout.
// ---------------------------------------------------------------------------
template <bool PERM_A, bool PERM_OUT>
__global__ __launch_bounds__(128)
void gemm_nt(const float* __restrict__ A,
             const float* __restrict__ W0,
             const float* __restrict__ W1,
             const float* __restrict__ W2,
             float* __restrict__ Cext)
{
    __shared__ float As[2][16][68];    // [buf][k][m]  64 + pad
    __shared__ float Bs[2][16][136];   // [buf][k][2n] duplicated cols + pad

    const int tid = threadIdx.x;
    const int tx  = tid & 15;      // n microtile (4 cols)
    const int ty  = tid >> 4;      // m microtile (8 rows = 4 packed pairs)
    const int m0  = blockIdx.y * 64;
    const int n0  = blockIdx.x * 64;
    const int sel = blockIdx.z;

    const float* W = (sel == 0) ? W0 : (sel == 1) ? W1 : W2;

    const int ar = tid >> 1;        // 0..63 A row within tile
    const int ak = (tid & 1) * 8;   // 0/8   A k-offset
    const int br = tid >> 1;        // 0..63 B row (n) within tile
    const int bk = (tid & 1) * 8;

    u64 acc[4][4];
#pragma unroll
    for (int r = 0; r < 4; r++)
#pragma unroll
        for (int c = 0; c < 4; c++) acc[r][c] = 0ull;

    float4 ra0, ra1, rb0, rb1;

    auto loadG = [&](int k0) {
        const float* ap;
        const int m = m0 + ar;
        if (PERM_A) {
            const int b = m / SEQ, l = m - b * SEQ;
            const int e = k0 + ak;
            const int h = e >> 6, d = e & 63;
            ap = g_ctx + (((b * NHEADS + h) * SEQ + l) * HD + d);
        } else {
            ap = A + m * EMB + k0 + ak;
        }
        ra0 = *(const float4*)ap;
        ra1 = *(const float4*)(ap + 4);
        const float* bp = W + (n0 + br) * EMB + k0 + bk;
        rb0 = *(const float4*)bp;
        rb1 = *(const float4*)(bp + 4);
    };
    auto storeS = [&](int buf) {
        As[buf][ak + 0][ar] = ra0.x; As[buf][ak + 1][ar] = ra0.y;
        As[buf][ak + 2][ar] = ra0.z; As[buf][ak + 3][ar] = ra0.w;
        As[buf][ak + 4][ar] = ra1.x; As[buf][ak + 5][ar] = ra1.y;
        As[buf][ak + 6][ar] = ra1.z; As[buf][ak + 7][ar] = ra1.w;
        const float bvals[8] = {rb0.x, rb0.y, rb0.z, rb0.w, rb1.x, rb1.y, rb1.z, rb1.w};
#pragma unroll
        for (int c = 0; c < 8; c++)
            *(float2*)&Bs[buf][bk + c][br * 2] = make_float2(bvals[c], bvals[c]);
    };

    loadG(0);
    storeS(0);
    __syncthreads();

    int cur = 0;
    for (int k0 = 0; k0 < EMB; k0 += 16) {
        const bool more = (k0 + 16 < EMB);
        if (more) loadG(k0 + 16);

#pragma unroll
        for (int kk = 0; kk < 16; kk++) {
            const ulonglong2 aA = *(const ulonglong2*)&As[cur][kk][ty * 8];
            const ulonglong2 aB = *(const ulonglong2*)&As[cur][kk][ty * 8 + 4];
            const ulonglong2 bA = *(const ulonglong2*)&Bs[cur][kk][tx * 8];
            const ulonglong2 bB = *(const ulonglong2*)&Bs[cur][kk][tx * 8 + 4];
            const u64 am[4] = {aA.x, aA.y, aB.x, aB.y};
            const u64 bn[4] = {bA.x, bA.y, bB.x, bB.y};
#pragma unroll
            for (int r = 0; r < 4; r++)
#pragma unroll
                for (int c = 0; c < 4; c++)
                    acc[r][c] = f2fma(am[r], bn[c], acc[r][c]);
        }

        if (more) {
            storeS(cur ^ 1);
            __syncthreads();
            cur ^= 1;
        }
    }

    float* C = Cext;
    bool do_norm = false;
    if (PERM_OUT) {
        C = (sel == 0) ? g_q : (sel == 1) ? g_k : g_v;
        do_norm = (sel < 2);
    }

#pragma unroll
    for (int r = 0; r < 4; r++) {
        float v0[4], v1[4];
#pragma unroll
        for (int c = 0; c < 4; c++) f2upk(acc[r][c], v0[c], v1[c]);
#pragma unroll
        for (int h = 0; h < 2; h++) {
            const float* vv = h ? v1 : v0;
            const int m = m0 + ty * 8 + r * 2 + h;
            const int f = n0 + tx * 4;          // one quaternion atom
            float4 o = make_float4(vv[0], vv[1], vv[2], vv[3]);
            if (do_norm) {
                const float d2 = o.x * o.x + o.y * o.y + o.z * o.z + o.w * o.w;
                const float inv = __fdividef(1.0f, sqrtf(d2) + 1e-12f);
                o.x *= inv; o.y *= inv; o.z *= inv; o.w *= inv;
            }
            if (PERM_OUT) {
                const int b = m / SEQ, l = m - b * SEQ;
                const int hh = f >> 6, d = f & 63;
                *(float4*)(C + (((b * NHEADS + hh) * SEQ + l) * HD + d)) = o;
            } else {
                *(float4*)(C + m * EMB + f) = o;
            }
        }
    }
}

// ---------------------------------------------------------------------------
// Attention core. 4 lanes per query row; each lane owns 4 atoms packed as two
// f32x2 groups: group g covers atoms (lane+4g, lane+4g+8). All quaternion math
// runs on the packed f32x2 pipe with pre-negated q components.
// ---------------------------------------------------------------------------
__device__ __forceinline__ float sigm(float x)
{
    return __fdividef(1.0f, 1.0f + __expf(-x));
}

#define TJ 64  // j-tile staged in smem

__global__ __launch_bounds__(128)
void attn_core(const float* __restrict__ dde_w, const float* __restrict__ dde_b)
{
    // pair-interleaved layout: per j (stride 68 floats):
    //   slot p (0..7) at [p*8 .. p*8+7] = {cA0,cB0, cA1,cB1, cA2,cB2, cA3,cB3}
    //   where A = atom p, B = atom p+8 (a packed f32x2 per component).
    __shared__ float ks[TJ * 68];
    __shared__ float vs[TJ * 68];

    const int tid  = threadIdx.x;
    const int lane = tid & 3;                       // 4 lanes per row
    const int row  = blockIdx.x * 32 + (tid >> 2);  // query index i
    const int bh   = blockIdx.y;

    // gate weights, 1/16 (atom mean) pre-folded
    float w16[4][4], bb[4];
#pragma unroll
    for (int p = 0; p < 4; p++) {
        bb[p] = dde_b[p];
#pragma unroll
        for (int q = 0; q < 4; q++) w16[p][q] = dde_w[p * 4 + q] * 0.0625f;
    }

    const float* qp = g_q + (bh * SEQ + row) * HD;
    u64 qw[2], qx[2], qy[2], qz[2], nqx[2], nqy[2], nqz[2];
#pragma unroll
    for (int g = 0; g < 2; g++) {
        const int p = lane + 4 * g;
        const float4 a0 = *(const float4*)(qp + p * 4);
        const float4 a1 = *(const float4*)(qp + (p + 8) * 4);
        qw[g]  = f2pk(a0.x, a1.x);   qx[g]  = f2pk(a0.y, a1.y);
        qy[g]  = f2pk(a0.z, a1.z);   qz[g]  = f2pk(a0.w, a1.w);
        nqx[g] = f2pk(-a0.y, -a1.y); nqy[g] = f2pk(-a0.z, -a1.z);
        nqz[g] = f2pk(-a0.w, -a1.w);
    }
    const u64 M1 = f2pk(-1.0f, -1.0f);

    u64 cw[2] = {0ull, 0ull}, cx[2] = {0ull, 0ull};
    u64 cy[2] = {0ull, 0ull}, cz[2] = {0ull, 0ull};

    for (int j0 = 0; j0 < SEQ; j0 += TJ) {
        const float4* kg = (const float4*)(g_k + (bh * SEQ + j0) * HD);
        const float4* vg = (const float4*)(g_v + (bh * SEQ + j0) * HD);
#pragma unroll
        for (int t = 0; t < 8; t++) {           // 1024 float4 / 128 threads
            const int idx = tid + t * 128;
            const int j = idx >> 4, a = idx & 15;
            const int base = j * 68 + (a & 7) * 8 + (a >> 3);
            const float4 f = kg[idx];
            ks[base + 0] = f.x; ks[base + 2] = f.y;
            ks[base + 4] = f.z; ks[base + 6] = f.w;
            const float4 h = vg[idx];
            vs[base + 0] = h.x; vs[base + 2] = h.y;
            vs[base + 4] = h.z; vs[base + 6] = h.w;
        }
        __syncthreads();

#pragma unroll 2
        for (int j = 0; j < TJ; j++) {
            u64 sw[2], sx[2], sy[2], sz[2];
#pragma unroll
            for (int g = 0; g < 2; g++) {
                const int off = j * 68 + (lane + 4 * g) * 8;
                const ulonglong2 kwx = *(const ulonglong2*)&ks[off];
                const ulonglong2 kyz = *(const ulonglong2*)&ks[off + 4];
                const u64 kw = kwx.x, kx = kwx.y, ky = kyz.x, kz = kyz.y;
                sw[g] = f2fma(nqz[g], kz, f2fma(nqy[g], ky, f2fma(nqx[g], kx, f2mul(qw[g], kw))));
                sx[g] = f2fma(nqz[g], ky, f2fma(qy[g],  kz, f2fma(qx[g],  kw, f2mul(qw[g], kx))));
                sy[g] = f2fma(qz[g],  kx, f2fma(qy[g],  kw, f2fma(nqx[g], kz, f2mul(qw[g], ky))));
                sz[g] = f2fma(qz[g],  kw, f2fma(nqy[g], kx, f2fma(qx[g],  ky, f2mul(qw[g], kz))));
            }

            // sum over the 16 atoms: in-thread packed adds + horizontal + 2-level butterfly
            const u64 tw = f2add(sw[0], sw[1]);
            const u64 tx2 = f2add(sx[0], sx[1]);
            const u64 ty2 = f2add(sy[0], sy[1]);
            const u64 tz2 = f2add(sz[0], sz[1]);
            float a0, a1;
            f2upk(tw, a0, a1);  float s0 = a0 + a1;
            f2upk(tx2, a0, a1); float s1 = a0 + a1;
            f2upk(ty2, a0, a1); float s2 = a0 + a1;
            f2upk(tz2, a0, a1); float s3 = a0 + a1;
#pragma unroll
            for (int o = 1; o < 4; o <<= 1) {
                s0 += __shfl_xor_sync(0xffffffffu, s0, o);
                s1 += __shfl_xor_sync(0xffffffffu, s1, o);
                s2 += __shfl_xor_sync(0xffffffffu, s2, o);
                s3 += __shfl_xor_sync(0xffffffffu, s3, o);
            }

            const float g0 = sigm(fmaf(s0, w16[0][0], fmaf(s1, w16[0][1], fmaf(s2, w16[0][2], fmaf(s3, w16[0][3], bb[0])))));
            const float g1 = sigm(fmaf(s0, w16[1][0], fmaf(s1, w16[1][1], fmaf(s2, w16[1][2], fmaf(s3, w16[1][3], bb[1])))));
            const float g2 = sigm(fmaf(s0, w16[2][0], fmaf(s1, w16[2][1], fmaf(s2, w16[2][2], fmaf(s3, w16[2][3], bb[2])))));
            const float g3 = sigm(fmaf(s0, w16[3][0], fmaf(s1, w16[3][1], fmaf(s2, w16[3][2], fmaf(s3, w16[3][3], bb[3])))));
            const u64 gp0 = f2pk(g0, g0), gp1 = f2pk(g1, g1);
            const u64 gp2 = f2pk(g2, g2), gp3 = f2pk(g3, g3);

#pragma unroll
            for (int g = 0; g < 2; g++) {
                const u64 gsw = f2mul(sw[g], gp0);
                const u64 gsx = f2mul(sx[g], gp1);
                const u64 gsy = f2mul(sy[g], gp2);
                const u64 gsz = f2mul(sz[g], gp3);
                const u64 ngsx = f2mul(gsx, M1);
                const u64 ngsy = f2mul(gsy, M1);
                const u64 ngsz = f2mul(gsz, M1);

                const int off = j * 68 + (lane + 4 * g) * 8;
                const ulonglong2 vwx = *(const ulonglong2*)&vs[off];
                const ulonglong2 vyz = *(const ulonglong2*)&vs[off + 4];
                const u64 vw = vwx.x, vx = vwx.y, vy = vyz.x, vz = vyz.y;

                cw[g] = f2fma(ngsz, vz, f2fma(ngsy, vy, f2fma(ngsx, vx, f2fma(gsw, vw, cw[g]))));
                cx[g] = f2fma(ngsz, vy, f2fma(gsy,  vz, f2fma(gsx,  vw, f2fma(gsw, vx, cx[g]))));
                cy[g] = f2fma(gsz,  vx, f2fma(gsy,  vw, f2fma(ngsx, vz, f2fma(gsw, vy, cy[g]))));
                cz[g] = f2fma(gsz,  vw, f2fma(ngsy, vx, f2fma(gsx,  vy, f2fma(gsw, vz, cz[g]))));
            }
        }
        __syncthreads();
    }

    float* cp = g_ctx + (bh * SEQ + row) * HD;
#pragma unroll
    for (int g = 0; g < 2; g++) {
        const int p = lane + 4 * g;
        float w0, w1, x0, x1, y0, y1, z0, z1;
        f2upk(cw[g], w0, w1); f2upk(cx[g], x0, x1);
        f2upk(cy[g], y0, y1); f2upk(cz[g], z0, z1);
        *(float4*)(cp + p * 4)       = make_float4(w0, x0, y0, z0);
        *(float4*)(cp + (p + 8) * 4) = make_float4(w1, x1, y1, z1);
    }
}

// ---------------------------------------------------------------------------
extern "C" void kernel_launch(void* const* d_in, const int* in_sizes, int n_in,
                              void* d_out, int out_size)
{
    (void)in_sizes; (void)n_in; (void)out_size;
    const float* x  = (const float*)d_in[0];
    const float* Wq = (const float*)d_in[1];
    const float* Wk = (const float*)d_in[2];
    const float* Wv = (const float*)d_in[3];
    const float* Wo = (const float*)d_in[4];
    const float* dw = (const float*)d_in[5];
    const float* db = (const float*)d_in[6];
    float* out = (float*)d_out;

    // QKV projections (fused over grid.z), normalization fused in epilogue
    dim3 gqkv(EMB / 64, MR / 64, 3);    // (8, 12, 3) = 288 blocks
    gemm_nt<false, true><<<gqkv, 128>>>(x, Wq, Wk, Wv, nullptr);

    // Pairwise quaternion attention core
    attn_core<<<dim3(SEQ / 32, NBH), 128>>>(dw, db);

    // Output projection
    dim3 go(EMB / 64, MR / 64, 1);      // (8, 12) = 96 blocks
    gemm_nt<true, false><<<go, 128>>>(nullptr, Wo, Wo, Wo, out);
}

// round 7
// speedup vs baseline: 1.2207x; 1.2207x over previous
#include <cuda_runtime.h>
#include <math.h>

#define BATCH  2
#define SEQ    384
#define EMB    512
#define NHEADS 8
#define HD     64
#define NBH    16      // BATCH*NHEADS
#define MR     768     // BATCH*SEQ

// Scratch (allocation-free rule: __device__ globals)
__device__ float g_q[NBH * SEQ * HD];   // normalized q-hat, [bh][l][64]
__device__ float g_k[NBH * SEQ * HD];   // normalized k-hat
__device__ float g_v[NBH * SEQ * HD];   // raw v
__device__ float g_ctx[NBH * SEQ * HD]; // attention output

// ---------------------------------------------------------------------------
// GEMM: C = A @ W^T.  M=768, N=512, K=512. Both operands K-major.
// BM=64, BN=64, BK=16, 256 threads, 4x4 microtile, double-buffered smem
// (one __syncthreads per k-tile; global prefetch overlaps the MMA loop).
// PERM_OUT: scatter output to [bh][l][64] layout (+ fused per-atom quaternion
//           normalization: ||H(q,k)|| = ||q||*||k|| lets us normalize q,k once).
// PERM_A:   gather A from g_ctx in [bh][l][64] layout.
// QKV: gridDim.z = 3 selects W / destination / norm.
// ---------------------------------------------------------------------------
template <bool PERM_A, bool PERM_OUT>
__global__ __launch_bounds__(256)
void gemm_nt(const float* __restrict__ A,
             const float* __restrict__ W0,
             const float* __restrict__ W1,
             const float* __restrict__ W2,
             float* __restrict__ Cext)
{
    __shared__ float As[2][16][68];   // [buf][k][m], padded
    __shared__ float Bs[2][16][68];   // [buf][k][n], padded

    const int tid = threadIdx.x;
    const int tx  = tid & 15;       // n microtile (4 cols)
    const int ty  = tid >> 4;       // m microtile (4 rows)
    const int m0  = blockIdx.y * 64;
    const int n0  = blockIdx.x * 64;
    const int sel = blockIdx.z;     // 0/1/2 for QKV, 0 for O-proj

    const float* W = (sel == 0) ? W0 : (sel == 1) ? W1 : W2;

    const int ar = tid >> 2;        // 0..63 tile row (A and B)
    const int ak = (tid & 3) * 4;   // 0,4,8,12 k-offset

    float acc[4][4];
#pragma unroll
    for (int i = 0; i < 4; i++)
#pragma unroll
        for (int j = 0; j < 4; j++) acc[i][j] = 0.0f;

    float4 ra, rb;

    auto loadG = [&](int k0) {
        const float* ap;
        const int m = m0 + ar;
        if (PERM_A) {
            const int b = m / SEQ, l = m - b * SEQ;
            const int e = k0 + ak;           // 4-aligned, stays within a head
            const int h = e >> 6, d = e & 63;
            ap = g_ctx + (((b * NHEADS + h) * SEQ + l) * HD + d);
        } else {
            ap = A + m * EMB + k0 + ak;
        }
        ra = *(const float4*)ap;
        rb = *(const float4*)(W + (n0 + ar) * EMB + k0 + ak);
    };
    auto storeS = [&](int buf) {
        As[buf][ak + 0][ar] = ra.x; As[buf][ak + 1][ar] = ra.y;
        As[buf][ak + 2][ar] = ra.z; As[buf][ak + 3][ar] = ra.w;
        Bs[buf][ak + 0][ar] = rb.x; Bs[buf][ak + 1][ar] = rb.y;
        Bs[buf][ak + 2][ar] = rb.z; Bs[buf][ak + 3][ar] = rb.w;
    };

    loadG(0);
    storeS(0);
    __syncthreads();

    int cur = 0;
    for (int k0 = 0; k0 < EMB; k0 += 16) {
        const bool more = (k0 + 16 < EMB);
        if (more) loadG(k0 + 16);

#pragma unroll
        for (int kk = 0; kk < 16; kk++) {
            const float4 a4 = *(const float4*)&As[cur][kk][ty * 4];
            const float4 b4 = *(const float4*)&Bs[cur][kk][tx * 4];
            const float am[4] = {a4.x, a4.y, a4.z, a4.w};
            const float bn[4] = {b4.x, b4.y, b4.z, b4.w};
#pragma unroll
            for (int i = 0; i < 4; i++)
#pragma unroll
                for (int j = 0; j < 4; j++)
                    acc[i][j] = fmaf(am[i], bn[j], acc[i][j]);
        }

        if (more) {
            storeS(cur ^ 1);
            __syncthreads();
            cur ^= 1;
        }
    }

    float* C = Cext;
    bool do_norm = false;
    if (PERM_OUT) {
        C = (sel == 0) ? g_q : (sel == 1) ? g_k : g_v;
        do_norm = (sel < 2);   // normalize q and k, not v
    }

#pragma unroll
    for (int i = 0; i < 4; i++) {
        const int m = m0 + ty * 4 + i;
        const int f = n0 + tx * 4;    // 4 consecutive cols == one atom
        float4 r = make_float4(acc[i][0], acc[i][1], acc[i][2], acc[i][3]);
        if (do_norm) {
            const float d2 = r.x * r.x + r.y * r.y + r.z * r.z + r.w * r.w;
            const float inv = __fdividef(1.0f, sqrtf(d2) + 1e-12f);
            r.x *= inv; r.y *= inv; r.z *= inv; r.w *= inv;
        }
        if (PERM_OUT) {
            const int b = m / SEQ, l = m - b * SEQ;
            const int h = f >> 6, d = f & 63;
            *(float4*)(C + (((b * NHEADS + h) * SEQ + l) * HD + d)) = r;
        } else {
            *(float4*)(C + m * EMB + f) = r;
        }
    }
}

// ---------------------------------------------------------------------------
// Attention core (R4 scalar version — known good at ~105us)
// ---------------------------------------------------------------------------
__device__ __forceinline__ float4 qmul(const float4 a, const float4 b)
{
    // components: .x=w .y=x .z=y .w=z
    float4 r;
    r.x = fmaf(a.x, b.x, fmaf(-a.y, b.y, fmaf(-a.z, b.z, -a.w * b.w)));
    r.y = fmaf(a.x, b.y, fmaf( a.y, b.x, fmaf( a.z, b.w, -a.w * b.z)));
    r.z = fmaf(a.x, b.z, fmaf(-a.y, b.w, fmaf( a.z, b.x,  a.w * b.y)));
    r.w = fmaf(a.x, b.w, fmaf( a.y, b.z, fmaf(-a.z, b.y,  a.w * b.x)));
    return r;
}

__device__ __forceinline__ void qmul_acc(float4& c, const float4 a, const float4 b)
{
    c.x = fmaf(a.x, b.x, fmaf(-a.y, b.y, fmaf(-a.z, b.z, fmaf(-a.w, b.w, c.x))));
    c.y = fmaf(a.x, b.y, fmaf( a.y, b.x, fmaf( a.z, b.w, fmaf(-a.w, b.z, c.y))));
    c.z = fmaf(a.x, b.z, fmaf(-a.y, b.w, fmaf( a.z, b.x, fmaf( a.w, b.y, c.z))));
    c.w = fmaf(a.x, b.w, fmaf( a.y, b.z, fmaf(-a.z, b.y, fmaf( a.w, b.x, c.w))));
}

__device__ __forceinline__ float sigm(float x)
{
    return __fdividef(1.0f, 1.0f + __expf(-x));
}

#define TJ 64  // j-tile staged in smem

__global__ __launch_bounds__(128)
void attn_core(const float* __restrict__ dde_w, const float* __restrict__ dde_b)
{
    __shared__ float4 ks4[TJ * 16];  // 16KB : k-hat tile [j][atom]
    __shared__ float4 vs4[TJ * 16];  // 16KB : v tile

    const int tid  = threadIdx.x;
    const int lane = tid & 7;                      // handles atoms lane, lane+8
    const int row  = blockIdx.x * 16 + (tid >> 3); // query index i
    const int bh   = blockIdx.y;

    // gate weights, 1/16 (atom mean) pre-folded
    float w16[4][4], bb[4];
#pragma unroll
    for (int p = 0; p < 4; p++) {
        bb[p] = dde_b[p];
#pragma unroll
        for (int q = 0; q < 4; q++) w16[p][q] = dde_w[p * 4 + q] * 0.0625f;
    }

    const float* qp = g_q + (bh * SEQ + row) * HD;
    const float4 qA = *(const float4*)(qp + lane * 4);
    const float4 qB = *(const float4*)(qp + (lane + 8) * 4);
    float4 cA = make_float4(0.f, 0.f, 0.f, 0.f);
    float4 cB = make_float4(0.f, 0.f, 0.f, 0.f);

    for (int j0 = 0; j0 < SEQ; j0 += TJ) {
        const float4* kg = (const float4*)(g_k + (bh * SEQ + j0) * HD);
        const float4* vg = (const float4*)(g_v + (bh * SEQ + j0) * HD);
#pragma unroll
        for (int t = 0; t < (TJ * 16) / 128; t++) {  // 8 float4s per thread each
            ks4[tid + t * 128] = kg[tid + t * 128];
            vs4[tid + t * 128] = vg[tid + t * 128];
        }
        __syncthreads();

#pragma unroll 4
        for (int j = 0; j < TJ; j++) {
            const float4 kA = ks4[j * 16 + lane];
            const float4 kB = ks4[j * 16 + lane + 8];
            const float4 sA = qmul(qA, kA);     // unit spinor, atom lane
            const float4 sB = qmul(qB, kB);     // unit spinor, atom lane+8

            // sum of spinor over all 16 atoms (pairs + 8-lane butterfly)
            float s0 = sA.x + sB.x, s1 = sA.y + sB.y;
            float s2 = sA.z + sB.z, s3 = sA.w + sB.w;
#pragma unroll
            for (int off = 1; off < 8; off <<= 1) {
                s0 += __shfl_xor_sync(0xffffffffu, s0, off);
                s1 += __shfl_xor_sync(0xffffffffu, s1, off);
                s2 += __shfl_xor_sync(0xffffffffu, s2, off);
                s3 += __shfl_xor_sync(0xffffffffu, s3, off);
            }

            const float g0 = sigm(fmaf(s0, w16[0][0], fmaf(s1, w16[0][1], fmaf(s2, w16[0][2], fmaf(s3, w16[0][3], bb[0])))));
            const float g1 = sigm(fmaf(s0, w16[1][0], fmaf(s1, w16[1][1], fmaf(s2, w16[1][2], fmaf(s3, w16[1][3], bb[1])))));
            const float g2 = sigm(fmaf(s0, w16[2][0], fmaf(s1, w16[2][1], fmaf(s2, w16[2][2], fmaf(s3, w16[2][3], bb[2])))));
            const float g3 = sigm(fmaf(s0, w16[3][0], fmaf(s1, w16[3][1], fmaf(s2, w16[3][2], fmaf(s3, w16[3][3], bb[3])))));

            const float4 vA = vs4[j * 16 + lane];
            const float4 vB = vs4[j * 16 + lane + 8];
            const float4 gA = make_float4(sA.x * g0, sA.y * g1, sA.z * g2, sA.w * g3);
            const float4 gB = make_float4(sB.x * g0, sB.y * g1, sB.z * g2, sB.w * g3);
            qmul_acc(cA, gA, vA);
            qmul_acc(cB, gB, vB);
        }
        __syncthreads();
    }

    float* cp = g_ctx + (bh * SEQ + row) * HD;
    *(float4*)(cp + lane * 4)       = cA;
    *(float4*)(cp + (lane + 8) * 4) = cB;
}

// ---------------------------------------------------------------------------
extern "C" void kernel_launch(void* const* d_in, const int* in_sizes, int n_in,
                              void* d_out, int out_size)
{
    (void)in_sizes; (void)n_in; (void)out_size;
    const float* x  = (const float*)d_in[0];
    const float* Wq = (const float*)d_in[1];
    const float* Wk = (const float*)d_in[2];
    const float* Wv = (const float*)d_in[3];
    const float* Wo = (const float*)d_in[4];
    const float* dw = (const float*)d_in[5];
    const float* db = (const float*)d_in[6];
    float* out = (float*)d_out;

    // QKV projections (fused over grid.z), normalization fused in epilogue
    dim3 gqkv(EMB / 64, MR / 64, 3);    // (8, 12, 3) = 288 blocks
    gemm_nt<false, true><<<gqkv, 256>>>(x, Wq, Wk, Wv, nullptr);

    // Pairwise quaternion attention core
    attn_core<<<dim3(SEQ / 16, NBH), 128>>>(dw, db);

    // Output projection
    dim3 go(EMB / 64, MR / 64, 1);      // (8, 12) = 96 blocks
    gemm_nt<true, false><<<go, 256>>>(nullptr, Wo, Wo, Wo, out);
}

// round 11
// speedup vs baseline: 1.3618x; 1.1156x over previous
#include <cuda_runtime.h>
#include <math.h>

#define BATCH  2
#define SEQ    384
#define EMB    512
#define NHEADS 8
#define HD     64
#define NBH    16      // BATCH*NHEADS
#define MR     768     // BATCH*SEQ

// Scratch (allocation-free rule: __device__ globals)
__device__ float g_q[NBH * SEQ * HD];    // normalized q-hat, [bh][l][64]
__device__ float g_k[NBH * SEQ * HD];    // normalized k-hat
__device__ float g_v[NBH * SEQ * HD];    // raw v
__device__ float g_ctx[NBH * SEQ * HD];  // attention output, j-half 0
__device__ float g_ctx2[NBH * SEQ * HD]; // attention output, j-half 1

// ---------------------------------------------------------------------------
// GEMM: C = A @ W^T.  M=768, N=512, K=512. Both operands K-major.
// BM=64, BN=64, BK=16, 256 threads, 4x4 microtile, double-buffered smem.
// PERM_OUT: scatter output to [bh][l][64] layout (+ fused per-atom quaternion
//           normalization: ||H(q,k)|| = ||q||*||k|| lets us normalize q,k once).
// PERM_A:   gather A = g_ctx + g_ctx2 (split-j partials) in [bh][l][64] layout.
// QKV: gridDim.z = 3 selects W / destination / norm.
// ---------------------------------------------------------------------------
template <bool PERM_A, bool PERM_OUT>
__global__ __launch_bounds__(256)
void gemm_nt(const float* __restrict__ A,
             const float* __restrict__ W0,
             const float* __restrict__ W1,
             const float* __restrict__ W2,
             float* __restrict__ Cext)
{
    __shared__ float As[2][16][68];   // [buf][k][m], padded
    __shared__ float Bs[2][16][68];   // [buf][k][n], padded

    const int tid = threadIdx.x;
    const int tx  = tid & 15;       // n microtile (4 cols)
    const int ty  = tid >> 4;       // m microtile (4 rows)
    const int m0  = blockIdx.y * 64;
    const int n0  = blockIdx.x * 64;
    const int sel = blockIdx.z;     // 0/1/2 for QKV, 0 for O-proj

    const float* W = (sel == 0) ? W0 : (sel == 1) ? W1 : W2;

    const int ar = tid >> 2;        // 0..63 tile row (A and B)
    const int ak = (tid & 3) * 4;   // 0,4,8,12 k-offset

    float acc[4][4];
#pragma unroll
    for (int i = 0; i < 4; i++)
#pragma unroll
        for (int j = 0; j < 4; j++) acc[i][j] = 0.0f;

    float4 ra, rb;

    auto loadG = [&](int k0) {
        const int m = m0 + ar;
        if (PERM_A) {
            const int b = m / SEQ, l = m - b * SEQ;
            const int e = k0 + ak;           // 4-aligned, stays within a head
            const int h = e >> 6, d = e & 63;
            const int idx = ((b * NHEADS + h) * SEQ + l) * HD + d;
            const float4 r0 = *(const float4*)(g_ctx + idx);
            const float4 r1 = *(const float4*)(g_ctx2 + idx);
            ra = make_float4(r0.x + r1.x, r0.y + r1.y, r0.z + r1.z, r0.w + r1.w);
        } else {
            ra = *(const float4*)(A + m * EMB + k0 + ak);
        }
        rb = *(const float4*)(W + (n0 + ar) * EMB + k0 + ak);
    };
    auto storeS = [&](int buf) {
        As[buf][ak + 0][ar] = ra.x; As[buf][ak + 1][ar] = ra.y;
        As[buf][ak + 2][ar] = ra.z; As[buf][ak + 3][ar] = ra.w;
        Bs[buf][ak + 0][ar] = rb.x; Bs[buf][ak + 1][ar] = rb.y;
        Bs[buf][ak + 2][ar] = rb.z; Bs[buf][ak + 3][ar] = rb.w;
    };

    loadG(0);
    storeS(0);
    __syncthreads();

    int cur = 0;
    for (int k0 = 0; k0 < EMB; k0 += 16) {
        const bool more = (k0 + 16 < EMB);
        if (more) loadG(k0 + 16);

#pragma unroll
        for (int kk = 0; kk < 16; kk++) {
            const float4 a4 = *(const float4*)&As[cur][kk][ty * 4];
            const float4 b4 = *(const float4*)&Bs[cur][kk][tx * 4];
            const float am[4] = {a4.x, a4.y, a4.z, a4.w};
            const float bn[4] = {b4.x, b4.y, b4.z, b4.w};
#pragma unroll
            for (int i = 0; i < 4; i++)
#pragma unroll
                for (int j = 0; j < 4; j++)
                    acc[i][j] = fmaf(am[i], bn[j], acc[i][j]);
        }

        if (more) {
            storeS(cur ^ 1);
            __syncthreads();
            cur ^= 1;
        }
    }

    float* C = Cext;
    bool do_norm = false;
    if (PERM_OUT) {
        C = (sel == 0) ? g_q : (sel == 1) ? g_k : g_v;
        do_norm = (sel < 2);   // normalize q and k, not v
    }

#pragma unroll
    for (int i = 0; i < 4; i++) {
        const int m = m0 + ty * 4 + i;
        const int f = n0 + tx * 4;    // 4 consecutive cols == one atom
        float4 r = make_float4(acc[i][0], acc[i][1], acc[i][2], acc[i][3]);
        if (do_norm) {
            const float d2 = r.x * r.x + r.y * r.y + r.z * r.z + r.w * r.w;
            const float inv = __fdividef(1.0f, sqrtf(d2) + 1e-12f);
            r.x *= inv; r.y *= inv; r.z *= inv; r.w *= inv;
        }
        if (PERM_OUT) {
            const int b = m / SEQ, l = m - b * SEQ;
            const int h = f >> 6, d = f & 63;
            *(float4*)(C + (((b * NHEADS + h) * SEQ + l) * HD + d)) = r;
        } else {
            *(float4*)(C + m * EMB + f) = r;
        }
    }
}

// ---------------------------------------------------------------------------
// Attention core. 4 lanes per query row, 4 atoms per lane (atoms lane+4t).
// Gate computed distributed: lane p computes gate component p, then width-4
// shfl.idx broadcasts all four. j-range split in 2 via gridDim.z (exact:
// gates are per-pair, ctx is a sum over j); partials in g_ctx / g_ctx2.
// ---------------------------------------------------------------------------
__device__ __forceinline__ float4 qmul(const float4 a, const float4 b)
{
    // components: .x=w .y=x .z=y .w=z
    float4 r;
    r.x = fmaf(a.x, b.x, fmaf(-a.y, b.y, fmaf(-a.z, b.z, -a.w * b.w)));
    r.y = fmaf(a.x, b.y, fmaf( a.y, b.x, fmaf( a.z, b.w, -a.w * b.z)));
    r.z = fmaf(a.x, b.z, fmaf(-a.y, b.w, fmaf( a.z, b.x,  a.w * b.y)));
    r.w = fmaf(a.x, b.w, fmaf( a.y, b.z, fmaf(-a.z, b.y,  a.w * b.x)));
    return r;
}

__device__ __forceinline__ void qmul_acc(float4& c, const float4 a, const float4 b)
{
    c.x = fmaf(a.x, b.x, fmaf(-a.y, b.y, fmaf(-a.z, b.z, fmaf(-a.w, b.w, c.x))));
    c.y = fmaf(a.x, b.y, fmaf( a.y, b.x, fmaf( a.z, b.w, fmaf(-a.w, b.z, c.y))));
    c.z = fmaf(a.x, b.z, fmaf(-a.y, b.w, fmaf( a.z, b.x, fmaf( a.w, b.y, c.z))));
    c.w = fmaf(a.x, b.w, fmaf( a.y, b.z, fmaf(-a.z, b.y, fmaf( a.w, b.x, c.w))));
}

__device__ __forceinline__ float sigm(float x)
{
    return __fdividef(1.0f, 1.0f + __expf(-x));
}

#define TJ 64     // j-tile staged in smem
#define JHALF 192 // SEQ/2 per z-slice

__global__ __launch_bounds__(128)
void attn_core(const float* __restrict__ dde_w, const float* __restrict__ dde_b)
{
    __shared__ float4 ks4[TJ * 16];  // 16KB : k-hat tile [j][atom]
    __shared__ float4 vs4[TJ * 16];  // 16KB : v tile

    const int tid   = threadIdx.x;
    const int lane  = tid & 3;                       // 4 lanes per row
    const int row   = blockIdx.x * 32 + (tid >> 2);  // query index i
    const int bh    = blockIdx.y;
    const int jbase = blockIdx.z * JHALF;

    // this lane's gate row, 1/16 (atom mean) pre-folded
    const float wl0 = dde_w[lane * 4 + 0] * 0.0625f;
    const float wl1 = dde_w[lane * 4 + 1] * 0.0625f;
    const float wl2 = dde_w[lane * 4 + 2] * 0.0625f;
    const float wl3 = dde_w[lane * 4 + 3] * 0.0625f;
    const float bl  = dde_b[lane];

    const float* qp = g_q + (bh * SEQ + row) * HD;
    float4 q[4], c[4];
#pragma unroll
    for (int t = 0; t < 4; t++) {
        q[t] = *(const float4*)(qp + (lane + 4 * t) * 4);
        c[t] = make_float4(0.f, 0.f, 0.f, 0.f);
    }

    for (int j0 = jbase; j0 < jbase + JHALF; j0 += TJ) {
        const float4* kg = (const float4*)(g_k + (bh * SEQ + j0) * HD);
        const float4* vg = (const float4*)(g_v + (bh * SEQ + j0) * HD);
#pragma unroll
        for (int t = 0; t < 8; t++) {    // 1024 float4 / 128 threads
            ks4[tid + t * 128] = kg[tid + t * 128];
            vs4[tid + t * 128] = vg[tid + t * 128];
        }
        __syncthreads();

#pragma unroll 2
        for (int j = 0; j < TJ; j++) {
            float4 s[4];
#pragma unroll
            for (int t = 0; t < 4; t++) {
                const float4 k = ks4[j * 16 + lane + 4 * t];
                s[t] = qmul(q[t], k);
            }

            // sum spinor over all 16 atoms: in-thread + 2-level 4-lane butterfly
            float s0 = (s[0].x + s[1].x) + (s[2].x + s[3].x);
            float s1 = (s[0].y + s[1].y) + (s[2].y + s[3].y);
            float s2 = (s[0].z + s[1].z) + (s[2].z + s[3].z);
            float s3 = (s[0].w + s[1].w) + (s[2].w + s[3].w);
#pragma unroll
            for (int o = 1; o < 4; o <<= 1) {
                s0 += __shfl_xor_sync(0xffffffffu, s0, o);
                s1 += __shfl_xor_sync(0xffffffffu, s1, o);
                s2 += __shfl_xor_sync(0xffffffffu, s2, o);
                s3 += __shfl_xor_sync(0xffffffffu, s3, o);
            }

            // distributed gate: this lane computes its own component only
            const float gp = sigm(fmaf(s0, wl0, fmaf(s1, wl1, fmaf(s2, wl2, fmaf(s3, wl3, bl)))));
            const float g0 = __shfl_sync(0xffffffffu, gp, 0, 4);
            const float g1 = __shfl_sync(0xffffffffu, gp, 1, 4);
            const float g2 = __shfl_sync(0xffffffffu, gp, 2, 4);
            const float g3 = __shfl_sync(0xffffffffu, gp, 3, 4);

#pragma unroll
            for (int t = 0; t < 4; t++) {
                const float4 v = vs4[j * 16 + lane + 4 * t];
                const float4 gs = make_float4(s[t].x * g0, s[t].y * g1,
                                              s[t].z * g2, s[t].w * g3);
                qmul_acc(c[t], gs, v);
            }
        }
        __syncthreads();
    }

    float* cp = (blockIdx.z ? g_ctx2 : g_ctx) + (bh * SEQ + row) * HD;
#pragma unroll
    for (int t = 0; t < 4; t++)
        *(float4*)(cp + (lane + 4 * t) * 4) = c[t];
}

// ---------------------------------------------------------------------------
extern "C" void kernel_launch(void* const* d_in, const int* in_sizes, int n_in,
                              void* d_out, int out_size)
{
    (void)in_sizes; (void)n_in; (void)out_size;
    const float* x  = (const float*)d_in[0];
    const float* Wq = (const float*)d_in[1];
    const float* Wk = (const float*)d_in[2];
    const float* Wv = (const float*)d_in[3];
    const float* Wo = (const float*)d_in[4];
    const float* dw = (const float*)d_in[5];
    const float* db = (const float*)d_in[6];
    float* out = (float*)d_out;

    // QKV projections (fused over grid.z), normalization fused in epilogue
    dim3 gqkv(EMB / 64, MR / 64, 3);    // (8, 12, 3) = 288 blocks
    gemm_nt<false, true><<<gqkv, 256>>>(x, Wq, Wk, Wv, nullptr);

    // Pairwise quaternion attention core, j-range split in 2
    attn_core<<<dim3(SEQ / 32, NBH, 2), 128>>>(dw, db);

    // Output projection (gathers g_ctx + g_ctx2)
    dim3 go(EMB / 64, MR / 64, 1);      // (8, 12) = 96 blocks
    gemm_nt<true, false><<<go, 256>>>(nullptr, Wo, Wo, Wo, out);
}

// round 15
// speedup vs baseline: 1.4484x; 1.0637x over previous
#include <cuda_runtime.h>
#include <math.h>

#define BATCH  2
#define SEQ    384
#define EMB    512
#define NHEADS 8
#define HD     64
#define NBH    16      // BATCH*NHEADS
#define MR     768     // BATCH*SEQ
#define NSPLIT 4       // j-range split factor

// Scratch (allocation-free rule: __device__ globals)
__device__ float g_q[NBH * SEQ * HD];            // normalized q-hat, [bh][l][64]
__device__ float g_k[NBH * SEQ * HD];            // normalized k-hat
__device__ float g_v[NBH * SEQ * HD];            // raw v
__device__ float g_ctxp[NSPLIT][NBH * SEQ * HD]; // attention output partials

// ---------------------------------------------------------------------------
// GEMM: C = A @ W^T.  M=768, N=512, K=512. Both operands K-major.
// BM=64, BN=64, BK=16, 256 threads, 4x4 microtile, double-buffered smem.
// PERM_OUT: scatter output to [bh][l][64] layout (+ fused per-atom quaternion
//           normalization: ||H(q,k)|| = ||q||*||k|| lets us normalize q,k once).
// PERM_A:   gather A = sum of NSPLIT ctx partials in [bh][l][64] layout.
// QKV: gridDim.z = 3 selects W / destination / norm.
// ---------------------------------------------------------------------------
template <bool PERM_A, bool PERM_OUT>
__global__ __launch_bounds__(256)
void gemm_nt(const float* __restrict__ A,
             const float* __restrict__ W0,
             const float* __restrict__ W1,
             const float* __restrict__ W2,
             float* __restrict__ Cext)
{
    __shared__ float As[2][16][68];   // [buf][k][m], padded
    __shared__ float Bs[2][16][68];   // [buf][k][n], padded

    const int tid = threadIdx.x;
    const int tx  = tid & 15;       // n microtile (4 cols)
    const int ty  = tid >> 4;       // m microtile (4 rows)
    const int m0  = blockIdx.y * 64;
    const int n0  = blockIdx.x * 64;
    const int sel = blockIdx.z;     // 0/1/2 for QKV, 0 for O-proj

    const float* W = (sel == 0) ? W0 : (sel == 1) ? W1 : W2;

    const int ar = tid >> 2;        // 0..63 tile row (A and B)
    const int ak = (tid & 3) * 4;   // 0,4,8,12 k-offset

    float acc[4][4];
#pragma unroll
    for (int i = 0; i < 4; i++)
#pragma unroll
        for (int j = 0; j < 4; j++) acc[i][j] = 0.0f;

    float4 ra, rb;

    auto loadG = [&](int k0) {
        const int m = m0 + ar;
        if (PERM_A) {
            const int b = m / SEQ, l = m - b * SEQ;
            const int e = k0 + ak;           // 4-aligned, stays within a head
            const int h = e >> 6, d = e & 63;
            const int idx = ((b * NHEADS + h) * SEQ + l) * HD + d;
            const float4 r0 = *(const float4*)(g_ctxp[0] + idx);
            const float4 r1 = *(const float4*)(g_ctxp[1] + idx);
            const float4 r2 = *(const float4*)(g_ctxp[2] + idx);
            const float4 r3 = *(const float4*)(g_ctxp[3] + idx);
            ra = make_float4((r0.x + r1.x) + (r2.x + r3.x),
                             (r0.y + r1.y) + (r2.y + r3.y),
                             (r0.z + r1.z) + (r2.z + r3.z),
                             (r0.w + r1.w) + (r2.w + r3.w));
        } else {
            ra = *(const float4*)(A + m * EMB + k0 + ak);
        }
        rb = *(const float4*)(W + (n0 + ar) * EMB + k0 + ak);
    };
    auto storeS = [&](int buf) {
        As[buf][ak + 0][ar] = ra.x; As[buf][ak + 1][ar] = ra.y;
        As[buf][ak + 2][ar] = ra.z; As[buf][ak + 3][ar] = ra.w;
        Bs[buf][ak + 0][ar] = rb.x; Bs[buf][ak + 1][ar] = rb.y;
        Bs[buf][ak + 2][ar] = rb.z; Bs[buf][ak + 3][ar] = rb.w;
    };

    loadG(0);
    storeS(0);
    __syncthreads();

    int cur = 0;
    for (int k0 = 0; k0 < EMB; k0 += 16) {
        const bool more = (k0 + 16 < EMB);
        if (more) loadG(k0 + 16);

#pragma unroll
        for (int kk = 0; kk < 16; kk++) {
            const float4 a4 = *(const float4*)&As[cur][kk][ty * 4];
            const float4 b4 = *(const float4*)&Bs[cur][kk][tx * 4];
            const float am[4] = {a4.x, a4.y, a4.z, a4.w};
            const float bn[4] = {b4.x, b4.y, b4.z, b4.w};
#pragma unroll
            for (int i = 0; i < 4; i++)
#pragma unroll
                for (int j = 0; j < 4; j++)
                    acc[i][j] = fmaf(am[i], bn[j], acc[i][j]);
        }

        if (more) {
            storeS(cur ^ 1);
            __syncthreads();
            cur ^= 1;
        }
    }

    float* C = Cext;
    bool do_norm = false;
    if (PERM_OUT) {
        C = (sel == 0) ? g_q : (sel == 1) ? g_k : g_v;
        do_norm = (sel < 2);   // normalize q and k, not v
    }

#pragma unroll
    for (int i = 0; i < 4; i++) {
        const int m = m0 + ty * 4 + i;
        const int f = n0 + tx * 4;    // 4 consecutive cols == one atom
        float4 r = make_float4(acc[i][0], acc[i][1], acc[i][2], acc[i][3]);
        if (do_norm) {
            const float d2 = r.x * r.x + r.y * r.y + r.z * r.z + r.w * r.w;
            const float inv = __fdividef(1.0f, sqrtf(d2) + 1e-12f);
            r.x *= inv; r.y *= inv; r.z *= inv; r.w *= inv;
        }
        if (PERM_OUT) {
            const int b = m / SEQ, l = m - b * SEQ;
            const int h = f >> 6, d = f & 63;
            *(float4*)(C + (((b * NHEADS + h) * SEQ + l) * HD + d)) = r;
        } else {
            *(float4*)(C + m * EMB + f) = r;
        }
    }
}

// ---------------------------------------------------------------------------
// Attention core. 4 lanes per query row, 4 atoms per lane (atoms lane+4t).
// Gate computed distributed: lane p computes gate component p, then width-4
// shfl.idx broadcasts all four. j-range split in NSPLIT via gridDim.z (exact:
// gates are per-pair, ctx is a sum over j); partials in g_ctxp[z].
// ---------------------------------------------------------------------------
__device__ __forceinline__ float4 qmul(const float4 a, const float4 b)
{
    // components: .x=w .y=x .z=y .w=z
    float4 r;
    r.x = fmaf(a.x, b.x, fmaf(-a.y, b.y, fmaf(-a.z, b.z, -a.w * b.w)));
    r.y = fmaf(a.x, b.y, fmaf( a.y, b.x, fmaf( a.z, b.w, -a.w * b.z)));
    r.z = fmaf(a.x, b.z, fmaf(-a.y, b.w, fmaf( a.z, b.x,  a.w * b.y)));
    r.w = fmaf(a.x, b.w, fmaf( a.y, b.z, fmaf(-a.z, b.y,  a.w * b.x)));
    return r;
}

__device__ __forceinline__ void qmul_acc(float4& c, const float4 a, const float4 b)
{
    c.x = fmaf(a.x, b.x, fmaf(-a.y, b.y, fmaf(-a.z, b.z, fmaf(-a.w, b.w, c.x))));
    c.y = fmaf(a.x, b.y, fmaf( a.y, b.x, fmaf( a.z, b.w, fmaf(-a.w, b.z, c.y))));
    c.z = fmaf(a.x, b.z, fmaf(-a.y, b.w, fmaf( a.z, b.x, fmaf( a.w, b.y, c.z))));
    c.w = fmaf(a.x, b.w, fmaf( a.y, b.z, fmaf(-a.z, b.y, fmaf( a.w, b.x, c.w))));
}

__device__ __forceinline__ float sigm(float x)
{
    return __fdividef(1.0f, 1.0f + __expf(-x));
}

#define TJ 48                  // j-tile staged in smem (24KB total)
#define JQ (SEQ / NSPLIT)      // 96 j's per z-slice

__global__ __launch_bounds__(128)
void attn_core(const float* __restrict__ dde_w, const float* __restrict__ dde_b)
{
    __shared__ float4 ks4[TJ * 16];  // 12KB : k-hat tile [j][atom]
    __shared__ float4 vs4[TJ * 16];  // 12KB : v tile

    const int tid   = threadIdx.x;
    const int lane  = tid & 3;                       // 4 lanes per row
    const int row   = blockIdx.x * 32 + (tid >> 2);  // query index i
    const int bh    = blockIdx.y;
    const int jbase = blockIdx.z * JQ;

    // this lane's gate row, 1/16 (atom mean) pre-folded
    const float wl0 = dde_w[lane * 4 + 0] * 0.0625f;
    const float wl1 = dde_w[lane * 4 + 1] * 0.0625f;
    const float wl2 = dde_w[lane * 4 + 2] * 0.0625f;
    const float wl3 = dde_w[lane * 4 + 3] * 0.0625f;
    const float bl  = dde_b[lane];

    const float* qp = g_q + (bh * SEQ + row) * HD;
    float4 q[4], c[4];
#pragma unroll
    for (int t = 0; t < 4; t++) {
        q[t] = *(const float4*)(qp + (lane + 4 * t) * 4);
        c[t] = make_float4(0.f, 0.f, 0.f, 0.f);
    }

    for (int j0 = jbase; j0 < jbase + JQ; j0 += TJ) {
        const float4* kg = (const float4*)(g_k + (bh * SEQ + j0) * HD);
        const float4* vg = (const float4*)(g_v + (bh * SEQ + j0) * HD);
#pragma unroll
        for (int t = 0; t < (TJ * 16) / 128; t++) {   // 6 float4s per thread
            ks4[tid + t * 128] = kg[tid + t * 128];
            vs4[tid + t * 128] = vg[tid + t * 128];
        }
        __syncthreads();

#pragma unroll 2
        for (int j = 0; j < TJ; j++) {
            float4 s[4];
#pragma unroll
            for (int t = 0; t < 4; t++) {
                const float4 k = ks4[j * 16 + lane + 4 * t];
                s[t] = qmul(q[t], k);
            }

            // sum spinor over all 16 atoms: in-thread + 2-level 4-lane butterfly
            float s0 = (s[0].x + s[1].x) + (s[2].x + s[3].x);
            float s1 = (s[0].y + s[1].y) + (s[2].y + s[3].y);
            float s2 = (s[0].z + s[1].z) + (s[2].z + s[3].z);
            float s3 = (s[0].w + s[1].w) + (s[2].w + s[3].w);
#pragma unroll
            for (int o = 1; o < 4; o <<= 1) {
                s0 += __shfl_xor_sync(0xffffffffu, s0, o);
                s1 += __shfl_xor_sync(0xffffffffu, s1, o);
                s2 += __shfl_xor_sync(0xffffffffu, s2, o);
                s3 += __shfl_xor_sync(0xffffffffu, s3, o);
            }

            // distributed gate: this lane computes its own component only
            const float gp = sigm(fmaf(s0, wl0, fmaf(s1, wl1, fmaf(s2, wl2, fmaf(s3, wl3, bl)))));
            const float g0 = __shfl_sync(0xffffffffu, gp, 0, 4);
            const float g1 = __shfl_sync(0xffffffffu, gp, 1, 4);
            const float g2 = __shfl_sync(0xffffffffu, gp, 2, 4);
            const float g3 = __shfl_sync(0xffffffffu, gp, 3, 4);

#pragma unroll
            for (int t = 0; t < 4; t++) {
                const float4 v = vs4[j * 16 + lane + 4 * t];
                const float4 gs = make_float4(s[t].x * g0, s[t].y * g1,
                                              s[t].z * g2, s[t].w * g3);
                qmul_acc(c[t], gs, v);
            }
        }
        __syncthreads();
    }

    float* cp = g_ctxp[blockIdx.z] + (bh * SEQ + row) * HD;
#pragma unroll
    for (int t = 0; t < 4; t++)
        *(float4*)(cp + (lane + 4 * t) * 4) = c[t];
}

// ---------------------------------------------------------------------------
extern "C" void kernel_launch(void* const* d_in, const int* in_sizes, int n_in,
                              void* d_out, int out_size)
{
    (void)in_sizes; (void)n_in; (void)out_size;
    const float* x  = (const float*)d_in[0];
    const float* Wq = (const float*)d_in[1];
    const float* Wk = (const float*)d_in[2];
    const float* Wv = (const float*)d_in[3];
    const float* Wo = (const float*)d_in[4];
    const float* dw = (const float*)d_in[5];
    const float* db = (const float*)d_in[6];
    float* out = (float*)d_out;

    // QKV projections (fused over grid.z), normalization fused in epilogue
    dim3 gqkv(EMB / 64, MR / 64, 3);    // (8, 12, 3) = 288 blocks
    gemm_nt<false, true><<<gqkv, 256>>>(x, Wq, Wk, Wv, nullptr);

    // Pairwise quaternion attention core, j-range split in NSPLIT
    attn_core<<<dim3(SEQ / 32, NBH, NSPLIT), 128>>>(dw, db);

    // Output projection (gathers sum of ctx partials)
    dim3 go(EMB / 64, MR / 64, 1);      // (8, 12) = 96 blocks
    gemm_nt<true, false><<<go, 256>>>(nullptr, Wo, Wo, Wo, out);
}